// round 15
// baseline (speedup 1.0000x reference)
#include <cuda_runtime.h>
#include <cstdio>

#define Bsz  8
#define Nn   8192
#define Ee   262144
#define FIN  64
#define Hh   128
#define FOUT 32
#define Mrows (Bsz*Nn)     // 65536 rows
#define EPSc 1e-5f

// ---------------- scratch (static device globals; no runtime alloc) ----------------
__device__ __align__(256) float g_h1 [(size_t)Mrows*Hh];   // 33.5 MB
__device__ __align__(256) float g_hc [(size_t)Mrows*Hh];   // 33.5 MB
__device__ __align__(256) float g_agg[(size_t)Mrows*Hh];   // 33.5 MB
__device__ __align__(256) float g_deg[Mrows];
__device__ __align__(256) float g_stats[6*Hh];             // 3 x {sum[H], sumsq[H]}
__device__ __align__(256) float g_Wf [Hh*Hh];
__device__ __align__(256) float g_bf [Hh];
__device__ __align__(256) float g_W1p[Hh*Hh];
__device__ __align__(256) float g_b1p[Hh];
__device__ __align__(256) float g_W2p[Hh*FOUT];
__device__ __align__(256) float g_b2p[FOUT];

// ---------------- init: zero agg, deg, stats ----------------
__global__ void init_zero_kernel() {
    int tid = blockIdx.x * blockDim.x + threadIdx.x;
    int stride = gridDim.x * blockDim.x;
    for (int i = tid; i < Mrows*Hh; i += stride) g_agg[i] = 0.f;
    if (tid < Mrows) g_deg[tid] = 0.f;
    if (tid < 6*Hh)  g_stats[tid] = 0.f;
}

// ---------------- generic row-tiled GEMM: Y[M,NOUT] = act(X[M,K] @ W[K,NOUT] + bias) ----------------
template<int K, int NOUT, bool RELU, int ROWS, int RCH>
__global__ void gemm_kernel(const float* __restrict__ X, const float* __restrict__ W,
                            const float* __restrict__ bias, float* __restrict__ Y)
{
    constexpr int NT = 128;
    constexpr int RG = NT / NOUT;          // row groups per block
    constexpr int CROWS = RCH * RG;        // rows per chunk
    extern __shared__ float smem[];
    float* Wsh = smem;                     // K*NOUT
    float* Xsh = smem + K*NOUT;            // CROWS*K

    int tid = threadIdx.x;
    int j   = tid % NOUT;
    int rg  = tid / NOUT;

    for (int i = tid; i < K*NOUT; i += NT) Wsh[i] = W[i];
    float bj = bias[j];

    int row0 = blockIdx.x * ROWS;
    for (int c = 0; c < ROWS; c += CROWS) {
        __syncthreads();   // protect Xsh reuse (and Wsh fill on first iter)
        for (int i = tid; i < CROWS*K; i += NT)
            Xsh[i] = X[(size_t)(row0 + c)*K + i];
        __syncthreads();

        float acc[RCH];
        #pragma unroll
        for (int r = 0; r < RCH; r++) acc[r] = bj;

        const float* xr = Xsh + rg*RCH*K;
        #pragma unroll 4
        for (int k = 0; k < K; k++) {
            float w = Wsh[k*NOUT + j];
            #pragma unroll
            for (int r = 0; r < RCH; r++)
                acc[r] = fmaf(xr[r*K + k], w, acc[r]);
        }
        #pragma unroll
        for (int r = 0; r < RCH; r++) {
            float v = acc[r];
            if (RELU) v = fmaxf(v, 0.f);
            Y[(size_t)(row0 + c + rg*RCH + r)*NOUT + j] = v;
        }
    }
}

// ---------------- per-channel stats (sum, sumsq) over all rows ----------------
__global__ void stats_kernel(const float* __restrict__ Xd, float* __restrict__ stat)
{
    int c = threadIdx.x;                   // 128 threads = channels
    float s = 0.f, s2 = 0.f;
    for (int row = blockIdx.x; row < Mrows; row += gridDim.x) {
        float v = Xd[(size_t)row*Hh + c];
        s += v;
        s2 = fmaf(v, v, s2);
    }
    atomicAdd(&stat[c],      s);
    atomicAdd(&stat[Hh + c], s2);
}

// ---------------- fold BN0 into (W02 @ Wc): Wf = diag(scale0) W02 Wc ; bf = (shift0 W02 + b02) Wc + bc ----------------
__global__ void fold_mid_kernel(const float* __restrict__ stat,
                                const float* __restrict__ W02, const float* __restrict__ b02,
                                const float* __restrict__ Wc,  const float* __restrict__ bc,
                                const float* __restrict__ bnw, const float* __restrict__ bnb)
{
    __shared__ float scale[Hh], shift[Hh], t[Hh];
    int tid = threadIdx.x;                 // 128
    float mean = stat[tid] / (float)Mrows;
    float var  = stat[Hh + tid] / (float)Mrows - mean*mean;
    float sc   = bnw[tid] * rsqrtf(var + EPSc);
    scale[tid] = sc;
    shift[tid] = bnb[tid] - mean*sc;
    __syncthreads();

    if (blockIdx.x < Hh) {
        int k = blockIdx.x, j = tid;
        float acc = 0.f;
        for (int m = 0; m < Hh; m++) acc = fmaf(W02[k*Hh + m], Wc[m*Hh + j], acc);
        g_Wf[k*Hh + j] = scale[k] * acc;
    } else {
        // bias path
        int m = tid;
        float acc = b02[m];
        for (int k = 0; k < Hh; k++) acc = fmaf(shift[k], W02[k*Hh + m], acc);
        t[m] = acc;
        __syncthreads();
        float bf = bc[tid];
        for (int m2 = 0; m2 < Hh; m2++) bf = fmaf(t[m2], Wc[m2*Hh + tid], bf);
        g_bf[tid] = bf;
    }
}

// ---------------- fold BN into a following linear: W' = diag(scale) W ; b' = b + shift @ W ----------------
template<int NOUT>
__global__ void fold_lin_kernel(const float* __restrict__ stat,
                                const float* __restrict__ W, const float* __restrict__ b,
                                const float* __restrict__ bnw, const float* __restrict__ bnb,
                                float* __restrict__ Wp, float* __restrict__ bp)
{
    __shared__ float scale[Hh], shift[Hh];
    int tid = threadIdx.x;                 // 128
    float mean = stat[tid] / (float)Mrows;
    float var  = stat[Hh + tid] / (float)Mrows - mean*mean;
    float sc   = bnw[tid] * rsqrtf(var + EPSc);
    scale[tid] = sc;
    shift[tid] = bnb[tid] - mean*sc;
    __syncthreads();

    for (int i = tid; i < Hh*NOUT; i += blockDim.x) {
        int k = i / NOUT;
        Wp[i] = scale[k] * W[i];
    }
    if (tid < NOUT) {
        float acc = b[tid];
        for (int k = 0; k < Hh; k++) acc = fmaf(shift[k], W[k*NOUT + tid], acc);
        bp[tid] = acc;
    }
}

// ---------------- SpMM edge scatter: one warp per edge, vectorized f32x4 reductions ----------------
__global__ void spmm_kernel(const int* __restrict__ rows, const int* __restrict__ cols,
                            const float* __restrict__ vals)
{
    int w    = (blockIdx.x * blockDim.x + threadIdx.x) >> 5;
    int lane = threadIdx.x & 31;
    if (w >= Bsz*Ee) return;
    int b = w / Ee;
    int r = rows[w];
    int c = cols[w];
    float v = vals[w];

    const float4* src = reinterpret_cast<const float4*>(g_hc + ((size_t)(b*Nn + c))*Hh);
    float4 x = src[lane];
    float* dst = g_agg + ((size_t)(b*Nn + r))*Hh + lane*4;
    asm volatile("red.global.add.v4.f32 [%0], {%1, %2, %3, %4};"
                 :: "l"(dst), "f"(x.x*v), "f"(x.y*v), "f"(x.z*v), "f"(x.w*v)
                 : "memory");
    if (lane == 0) atomicAdd(&g_deg[b*Nn + r], v);
}

// ---------------- degree-normalize + pad-mask + relu (in place on g_agg) ----------------
__global__ void norm_kernel(const int* __restrict__ num_nodes)
{
    int i = blockIdx.x * blockDim.x + threadIdx.x;
    if (i >= Mrows*Hh) return;
    int row = i >> 7;          // / H
    int b   = row >> 13;       // / N
    int n   = row & (Nn - 1);
    float d = fmaxf(g_deg[row], 1.0f);
    float vv = fmaxf(g_agg[i] / d, 0.f);
    if (n >= num_nodes[b]) vv = 0.f;
    g_agg[i] = vv;
}

// ---------------- launch ----------------
extern "C" void kernel_launch(void* const* d_in, const int* in_sizes, int n_in,
                              void* d_out, int out_size)
{
    (void)in_sizes; (void)n_in; (void)out_size;
    const float* x     = (const float*)d_in[0];
    const int*   erows = (const int*)  d_in[1];
    const int*   ecols = (const int*)  d_in[2];
    const float* evals = (const float*)d_in[3];
    const int*   nnod  = (const int*)  d_in[4];
    const float* W0  = (const float*)d_in[5],  *b0  = (const float*)d_in[6];
    const float* W02 = (const float*)d_in[7],  *b02 = (const float*)d_in[8];
    const float* Wc  = (const float*)d_in[9],  *bc  = (const float*)d_in[10];
    const float* W1  = (const float*)d_in[11], *b1  = (const float*)d_in[12];
    const float* W2  = (const float*)d_in[13], *b2  = (const float*)d_in[14];
    const float* bn0w= (const float*)d_in[15], *bn0b= (const float*)d_in[16];
    const float* bncw= (const float*)d_in[17], *bncb= (const float*)d_in[18];
    const float* bn1w= (const float*)d_in[19], *bn1b= (const float*)d_in[20];
    float* out = (float*)d_out;

    float *p_h1, *p_hc, *p_agg, *p_stats, *p_Wf, *p_bf, *p_W1p, *p_b1p, *p_W2p, *p_b2p;
    cudaGetSymbolAddress((void**)&p_h1,  g_h1);
    cudaGetSymbolAddress((void**)&p_hc,  g_hc);
    cudaGetSymbolAddress((void**)&p_agg, g_agg);
    cudaGetSymbolAddress((void**)&p_stats, g_stats);
    cudaGetSymbolAddress((void**)&p_Wf,  g_Wf);
    cudaGetSymbolAddress((void**)&p_bf,  g_bf);
    cudaGetSymbolAddress((void**)&p_W1p, g_W1p);
    cudaGetSymbolAddress((void**)&p_b1p, g_b1p);
    cudaGetSymbolAddress((void**)&p_W2p, g_W2p);
    cudaGetSymbolAddress((void**)&p_b2p, g_b2p);

    const int smem_g1   = (FIN*Hh + 4*FIN) * (int)sizeof(float);        // 33 KB
    const int smem_g128 = (Hh*Hh + 4*Hh)   * (int)sizeof(float);        // 66 KB -> needs opt-in
    const int smem_gout = (Hh*FOUT + 16*Hh)* (int)sizeof(float);        // 24 KB

    cudaFuncSetAttribute(gemm_kernel<Hh,Hh,false,32,4>,
                         cudaFuncAttributeMaxDynamicSharedMemorySize, smem_g128);
    cudaFuncSetAttribute(gemm_kernel<Hh,Hh,true,32,4>,
                         cudaFuncAttributeMaxDynamicSharedMemorySize, smem_g128);

    // 0) zero scratch
    init_zero_kernel<<<2048, 256>>>();

    // 1) h1 = relu(x @ W0 + b0)
    gemm_kernel<FIN,Hh,true,32,4><<<Mrows/32, 128, smem_g1>>>(x, W0, b0, p_h1);

    // 2) BN0 stats on h1
    stats_kernel<<<512, 128>>>(p_h1, p_stats + 0);

    // 3) fold BN0 + W02 + Wc into (Wf, bf)
    fold_mid_kernel<<<Hh + 1, Hh>>>(p_stats, W02, b02, Wc, bc, bn0w, bn0b);

    // 4) hc = h1 @ Wf + bf
    gemm_kernel<Hh,Hh,false,32,4><<<Mrows/32, 128, smem_g128>>>(p_h1, p_Wf, p_bf, p_hc);

    // 5) SpMM scatter + degree
    spmm_kernel<<<(Bsz*Ee*32)/256, 256>>>(erows, ecols, evals);

    // 6) normalize + mask + relu (in place -> h2 in g_agg)
    norm_kernel<<<(Mrows*Hh)/256, 256>>>(nnod);

    // 7) BNc stats
    stats_kernel<<<512, 128>>>(p_agg, p_stats + 2*Hh);

    // 8) fold BNc into W1
    fold_lin_kernel<Hh><<<1, 128>>>(p_stats + 2*Hh, W1, b1, bncw, bncb, p_W1p, p_b1p);

    // 9) h3 = relu(h2 @ W1' + b1')   (h3 reuses g_h1)
    gemm_kernel<Hh,Hh,true,32,4><<<Mrows/32, 128, smem_g128>>>(p_agg, p_W1p, p_b1p, p_h1);

    // 10) BN1 stats
    stats_kernel<<<512, 128>>>(p_h1, p_stats + 4*Hh);

    // 11) fold BN1 into W2
    fold_lin_kernel<FOUT><<<1, 128>>>(p_stats + 4*Hh, W2, b2, bn1w, bn1b, p_W2p, p_b2p);

    // 12) out = h3 @ W2' + b2'
    gemm_kernel<Hh,FOUT,false,32,4><<<Mrows/32, 128, smem_gout>>>(p_h1, p_W2p, p_b2p, out);
}

// round 16
// speedup vs baseline: 1.0026x; 1.0026x over previous
#include <cuda_runtime.h>
#include <cstdio>

#define Bsz  8
#define Nn   8192
#define Ee   262144
#define FIN  64
#define Hh   128
#define FOUT 32
#define Mrows (Bsz*Nn)     // 65536 rows
#define EPSc 1e-5f

// ---------------- scratch (static device globals; no runtime alloc) ----------------
__device__ __align__(256) float g_h1 [(size_t)Mrows*Hh];   // 33.5 MB
__device__ __align__(256) float g_hc [(size_t)Mrows*Hh];   // 33.5 MB
__device__ __align__(256) float g_agg[(size_t)Mrows*Hh];   // 33.5 MB
__device__ __align__(256) float g_deg[Mrows];
__device__ __align__(256) float g_stats[6*Hh];             // 3 x {sum[H], sumsq[H]}
__device__ __align__(256) float g_Wf [Hh*Hh];
__device__ __align__(256) float g_bf [Hh];
__device__ __align__(256) float g_W1p[Hh*Hh];
__device__ __align__(256) float g_b1p[Hh];
__device__ __align__(256) float g_W2p[Hh*FOUT];
__device__ __align__(256) float g_b2p[FOUT];

// ---------------- init: zero agg, deg, stats ----------------
__global__ void init_zero_kernel() {
    int tid = blockIdx.x * blockDim.x + threadIdx.x;
    int stride = gridDim.x * blockDim.x;
    for (int i = tid; i < Mrows*Hh; i += stride) g_agg[i] = 0.f;
    if (tid < Mrows) g_deg[tid] = 0.f;
    if (tid < 6*Hh)  g_stats[tid] = 0.f;
}

// ---------------- generic row-tiled GEMM: Y[M,NOUT] = act(X[M,K] @ W[K,NOUT] + bias) ----------------
template<int K, int NOUT, bool RELU, int ROWS, int RCH>
__global__ void gemm_kernel(const float* __restrict__ X, const float* __restrict__ W,
                            const float* __restrict__ bias, float* __restrict__ Y)
{
    constexpr int NT = 128;
    constexpr int RG = NT / NOUT;          // row groups per block
    constexpr int CROWS = RCH * RG;        // rows per chunk
    extern __shared__ float smem[];
    float* Wsh = smem;                     // K*NOUT
    float* Xsh = smem + K*NOUT;            // CROWS*K

    int tid = threadIdx.x;
    int j   = tid % NOUT;
    int rg  = tid / NOUT;

    for (int i = tid; i < K*NOUT; i += NT) Wsh[i] = W[i];
    float bj = bias[j];

    int row0 = blockIdx.x * ROWS;
    for (int c = 0; c < ROWS; c += CROWS) {
        __syncthreads();   // protect Xsh reuse (and Wsh fill on first iter)
        for (int i = tid; i < CROWS*K; i += NT)
            Xsh[i] = X[(size_t)(row0 + c)*K + i];
        __syncthreads();

        float acc[RCH];
        #pragma unroll
        for (int r = 0; r < RCH; r++) acc[r] = bj;

        const float* xr = Xsh + rg*RCH*K;
        #pragma unroll 4
        for (int k = 0; k < K; k++) {
            float w = Wsh[k*NOUT + j];
            #pragma unroll
            for (int r = 0; r < RCH; r++)
                acc[r] = fmaf(xr[r*K + k], w, acc[r]);
        }
        #pragma unroll
        for (int r = 0; r < RCH; r++) {
            float v = acc[r];
            if (RELU) v = fmaxf(v, 0.f);
            Y[(size_t)(row0 + c + rg*RCH + r)*NOUT + j] = v;
        }
    }
}

// ---------------- per-channel stats (sum, sumsq) over all rows ----------------
__global__ void stats_kernel(const float* __restrict__ Xd, float* __restrict__ stat)
{
    int c = threadIdx.x;                   // 128 threads = channels
    float s = 0.f, s2 = 0.f;
    for (int row = blockIdx.x; row < Mrows; row += gridDim.x) {
        float v = Xd[(size_t)row*Hh + c];
        s += v;
        s2 = fmaf(v, v, s2);
    }
    atomicAdd(&stat[c],      s);
    atomicAdd(&stat[Hh + c], s2);
}

// ---------------- fold BN0 into (W02 @ Wc): Wf = diag(scale0) W02 Wc ; bf = (shift0 W02 + b02) Wc + bc ----------------
__global__ void fold_mid_kernel(const float* __restrict__ stat,
                                const float* __restrict__ W02, const float* __restrict__ b02,
                                const float* __restrict__ Wc,  const float* __restrict__ bc,
                                const float* __restrict__ bnw, const float* __restrict__ bnb)
{
    __shared__ float scale[Hh], shift[Hh], t[Hh];
    int tid = threadIdx.x;                 // 128
    float mean = stat[tid] / (float)Mrows;
    float var  = stat[Hh + tid] / (float)Mrows - mean*mean;
    float sc   = bnw[tid] * rsqrtf(var + EPSc);
    scale[tid] = sc;
    shift[tid] = bnb[tid] - mean*sc;
    __syncthreads();

    if (blockIdx.x < Hh) {
        int k = blockIdx.x, j = tid;
        float acc = 0.f;
        for (int m = 0; m < Hh; m++) acc = fmaf(W02[k*Hh + m], Wc[m*Hh + j], acc);
        g_Wf[k*Hh + j] = scale[k] * acc;
    } else {
        // bias path
        int m = tid;
        float acc = b02[m];
        for (int k = 0; k < Hh; k++) acc = fmaf(shift[k], W02[k*Hh + m], acc);
        t[m] = acc;
        __syncthreads();
        float bf = bc[tid];
        for (int m2 = 0; m2 < Hh; m2++) bf = fmaf(t[m2], Wc[m2*Hh + tid], bf);
        g_bf[tid] = bf;
    }
}

// ---------------- fold BN into a following linear: W' = diag(scale) W ; b' = b + shift @ W ----------------
template<int NOUT>
__global__ void fold_lin_kernel(const float* __restrict__ stat,
                                const float* __restrict__ W, const float* __restrict__ b,
                                const float* __restrict__ bnw, const float* __restrict__ bnb,
                                float* __restrict__ Wp, float* __restrict__ bp)
{
    __shared__ float scale[Hh], shift[Hh];
    int tid = threadIdx.x;                 // 128
    float mean = stat[tid] / (float)Mrows;
    float var  = stat[Hh + tid] / (float)Mrows - mean*mean;
    float sc   = bnw[tid] * rsqrtf(var + EPSc);
    scale[tid] = sc;
    shift[tid] = bnb[tid] - mean*sc;
    __syncthreads();

    for (int i = tid; i < Hh*NOUT; i += blockDim.x) {
        int k = i / NOUT;
        Wp[i] = scale[k] * W[i];
    }
    if (tid < NOUT) {
        float acc = b[tid];
        for (int k = 0; k < Hh; k++) acc = fmaf(shift[k], W[k*NOUT + tid], acc);
        bp[tid] = acc;
    }
}

// ---------------- SpMM edge scatter: one warp per edge, vectorized f32x4 reductions ----------------
__global__ void spmm_kernel(const int* __restrict__ rows, const int* __restrict__ cols,
                            const float* __restrict__ vals)
{
    int w    = (blockIdx.x * blockDim.x + threadIdx.x) >> 5;
    int lane = threadIdx.x & 31;
    if (w >= Bsz*Ee) return;
    int b = w / Ee;
    int r = rows[w];
    int c = cols[w];
    float v = vals[w];

    const float4* src = reinterpret_cast<const float4*>(g_hc + ((size_t)(b*Nn + c))*Hh);
    float4 x = src[lane];
    float* dst = g_agg + ((size_t)(b*Nn + r))*Hh + lane*4;
    asm volatile("red.global.add.v4.f32 [%0], {%1, %2, %3, %4};"
                 :: "l"(dst), "f"(x.x*v), "f"(x.y*v), "f"(x.z*v), "f"(x.w*v)
                 : "memory");
    if (lane == 0) atomicAdd(&g_deg[b*Nn + r], v);
}

// ---------------- degree-normalize + pad-mask + relu (in place on g_agg) ----------------
__global__ void norm_kernel(const int* __restrict__ num_nodes)
{
    int i = blockIdx.x * blockDim.x + threadIdx.x;
    if (i >= Mrows*Hh) return;
    int row = i >> 7;          // / H
    int b   = row >> 13;       // / N
    int n   = row & (Nn - 1);
    float d = fmaxf(g_deg[row], 1.0f);
    float vv = fmaxf(g_agg[i] / d, 0.f);
    if (n >= num_nodes[b]) vv = 0.f;
    g_agg[i] = vv;
}

// ---------------- launch ----------------
extern "C" void kernel_launch(void* const* d_in, const int* in_sizes, int n_in,
                              void* d_out, int out_size)
{
    (void)in_sizes; (void)n_in; (void)out_size;
    const float* x     = (const float*)d_in[0];
    const int*   erows = (const int*)  d_in[1];
    const int*   ecols = (const int*)  d_in[2];
    const float* evals = (const float*)d_in[3];
    const int*   nnod  = (const int*)  d_in[4];
    const float* W0  = (const float*)d_in[5],  *b0  = (const float*)d_in[6];
    const float* W02 = (const float*)d_in[7],  *b02 = (const float*)d_in[8];
    const float* Wc  = (const float*)d_in[9],  *bc  = (const float*)d_in[10];
    const float* W1  = (const float*)d_in[11], *b1  = (const float*)d_in[12];
    const float* W2  = (const float*)d_in[13], *b2  = (const float*)d_in[14];
    const float* bn0w= (const float*)d_in[15], *bn0b= (const float*)d_in[16];
    const float* bncw= (const float*)d_in[17], *bncb= (const float*)d_in[18];
    const float* bn1w= (const float*)d_in[19], *bn1b= (const float*)d_in[20];
    float* out = (float*)d_out;

    float *p_h1, *p_hc, *p_agg, *p_stats, *p_Wf, *p_bf, *p_W1p, *p_b1p, *p_W2p, *p_b2p;
    cudaGetSymbolAddress((void**)&p_h1,  g_h1);
    cudaGetSymbolAddress((void**)&p_hc,  g_hc);
    cudaGetSymbolAddress((void**)&p_agg, g_agg);
    cudaGetSymbolAddress((void**)&p_stats, g_stats);
    cudaGetSymbolAddress((void**)&p_Wf,  g_Wf);
    cudaGetSymbolAddress((void**)&p_bf,  g_bf);
    cudaGetSymbolAddress((void**)&p_W1p, g_W1p);
    cudaGetSymbolAddress((void**)&p_b1p, g_b1p);
    cudaGetSymbolAddress((void**)&p_W2p, g_W2p);
    cudaGetSymbolAddress((void**)&p_b2p, g_b2p);

    const int smem_g1   = (FIN*Hh + 4*FIN) * (int)sizeof(float);        // 33 KB
    const int smem_g128 = (Hh*Hh + 4*Hh)   * (int)sizeof(float);        // 66 KB -> needs opt-in
    const int smem_gout = (Hh*FOUT + 16*Hh)* (int)sizeof(float);        // 24 KB

    cudaFuncSetAttribute(gemm_kernel<Hh,Hh,false,32,4>,
                         cudaFuncAttributeMaxDynamicSharedMemorySize, smem_g128);
    cudaFuncSetAttribute(gemm_kernel<Hh,Hh,true,32,4>,
                         cudaFuncAttributeMaxDynamicSharedMemorySize, smem_g128);

    // 0) zero scratch
    init_zero_kernel<<<2048, 256>>>();

    // 1) h1 = relu(x @ W0 + b0)
    gemm_kernel<FIN,Hh,true,32,4><<<Mrows/32, 128, smem_g1>>>(x, W0, b0, p_h1);

    // 2) BN0 stats on h1
    stats_kernel<<<512, 128>>>(p_h1, p_stats + 0);

    // 3) fold BN0 + W02 + Wc into (Wf, bf)
    fold_mid_kernel<<<Hh + 1, Hh>>>(p_stats, W02, b02, Wc, bc, bn0w, bn0b);

    // 4) hc = h1 @ Wf + bf
    gemm_kernel<Hh,Hh,false,32,4><<<Mrows/32, 128, smem_g128>>>(p_h1, p_Wf, p_bf, p_hc);

    // 5) SpMM scatter + degree
    spmm_kernel<<<(Bsz*Ee*32)/256, 256>>>(erows, ecols, evals);

    // 6) normalize + mask + relu (in place -> h2 in g_agg)
    norm_kernel<<<(Mrows*Hh)/256, 256>>>(nnod);

    // 7) BNc stats
    stats_kernel<<<512, 128>>>(p_agg, p_stats + 2*Hh);

    // 8) fold BNc into W1
    fold_lin_kernel<Hh><<<1, 128>>>(p_stats + 2*Hh, W1, b1, bncw, bncb, p_W1p, p_b1p);

    // 9) h3 = relu(h2 @ W1' + b1')   (h3 reuses g_h1)
    gemm_kernel<Hh,Hh,true,32,4><<<Mrows/32, 128, smem_g128>>>(p_agg, p_W1p, p_b1p, p_h1);

    // 10) BN1 stats
    stats_kernel<<<512, 128>>>(p_h1, p_stats + 4*Hh);

    // 11) fold BN1 into W2
    fold_lin_kernel<FOUT><<<1, 128>>>(p_stats + 4*Hh, W2, b2, bn1w, bn1b, p_W2p, p_b2p);

    // 12) out = h3 @ W2' + b2'
    gemm_kernel<Hh,FOUT,false,32,4><<<Mrows/32, 128, smem_gout>>>(p_h1, p_W2p, p_b2p, out);
}